// round 3
// baseline (speedup 1.0000x reference)
#include <cuda_runtime.h>
#include <math.h>

#define N_NODES 100000
#define IN_DIM 128
#define HIDDEN 64
#define N_EDGES 1600000

// Scratch (no allocations allowed — device globals)
__device__ float g_weights[N_NODES];
__device__ float g_readout[(size_t)N_NODES * IN_DIM];   // 51.2 MB
__device__ float g_hidden[(size_t)N_NODES * HIDDEN];    // 25.6 MB

// ---------------------------------------------------------------------------
// Zero the readout accumulator (graph replays need this every launch)
// ---------------------------------------------------------------------------
__global__ void zero_kernel() {
    int i = blockIdx.x * blockDim.x + threadIdx.x;
    if (i < N_NODES * IN_DIM / 4)
        reinterpret_cast<float4*>(g_readout)[i] = make_float4(0.f, 0.f, 0.f, 0.f);
}

// ---------------------------------------------------------------------------
// Gate: weights[i] = sigmoid( tanh(x_i @ W_sim + b_sim) @ w_vec + b_vec )
// Thread-per-node, W_sim in smem (float4 broadcast loads).
// ---------------------------------------------------------------------------
__global__ __launch_bounds__(256) void gate_kernel(
    const float* __restrict__ x, const float* __restrict__ W_sim,
    const float* __restrict__ b_sim, const float* __restrict__ w_vec,
    const float* __restrict__ b_vec)
{
    __shared__ float sW[IN_DIM * HIDDEN];   // 32 KB
    __shared__ float sb[HIDDEN];
    __shared__ float swv[HIDDEN];
    __shared__ float sbv;
    for (int i = threadIdx.x; i < IN_DIM * HIDDEN; i += 256) sW[i] = W_sim[i];
    if (threadIdx.x < HIDDEN) {
        sb[threadIdx.x]  = b_sim[threadIdx.x];
        swv[threadIdx.x] = w_vec[threadIdx.x];
    }
    if (threadIdx.x == 0) sbv = b_vec[0];
    __syncthreads();

    int node = blockIdx.x * 256 + threadIdx.x;
    if (node >= N_NODES) return;

    float h[HIDDEN];
    #pragma unroll
    for (int j = 0; j < HIDDEN; j++) h[j] = sb[j];

    const float4* x4 = reinterpret_cast<const float4*>(x + (size_t)node * IN_DIM);
    for (int k4 = 0; k4 < IN_DIM / 4; k4++) {
        float4 xv = x4[k4];
        const float4* w0 = reinterpret_cast<const float4*>(sW + (k4 * 4 + 0) * HIDDEN);
        const float4* w1 = reinterpret_cast<const float4*>(sW + (k4 * 4 + 1) * HIDDEN);
        const float4* w2 = reinterpret_cast<const float4*>(sW + (k4 * 4 + 2) * HIDDEN);
        const float4* w3 = reinterpret_cast<const float4*>(sW + (k4 * 4 + 3) * HIDDEN);
        #pragma unroll
        for (int j4 = 0; j4 < HIDDEN / 4; j4++) {
            float4 a = w0[j4], b = w1[j4], c = w2[j4], d = w3[j4];
            float h0 = h[4*j4+0], h1 = h[4*j4+1], h2 = h[4*j4+2], h3 = h[4*j4+3];
            h0 = fmaf(xv.x, a.x, h0); h0 = fmaf(xv.y, b.x, h0);
            h0 = fmaf(xv.z, c.x, h0); h0 = fmaf(xv.w, d.x, h0);
            h1 = fmaf(xv.x, a.y, h1); h1 = fmaf(xv.y, b.y, h1);
            h1 = fmaf(xv.z, c.y, h1); h1 = fmaf(xv.w, d.y, h1);
            h2 = fmaf(xv.x, a.z, h2); h2 = fmaf(xv.y, b.z, h2);
            h2 = fmaf(xv.z, c.z, h2); h2 = fmaf(xv.w, d.z, h2);
            h3 = fmaf(xv.x, a.w, h3); h3 = fmaf(xv.y, b.w, h3);
            h3 = fmaf(xv.z, c.w, h3); h3 = fmaf(xv.w, d.w, h3);
            h[4*j4+0] = h0; h[4*j4+1] = h1; h[4*j4+2] = h2; h[4*j4+3] = h3;
        }
    }

    float s = sbv;
    #pragma unroll
    for (int j = 0; j < HIDDEN; j++) s = fmaf(tanhf(h[j]), swv[j], s);
    g_weights[node] = 1.f / (1.f + expf(-s));
}

// ---------------------------------------------------------------------------
// Scatter: readout[row] += x[col] * weights[col], warp-per-edge.
// Vectorized no-return atomics (red.global.add.v4.f32, sm_90+).
// edge_index is int32 (JAX x64-disabled downcasts int64 -> int32).
// ---------------------------------------------------------------------------
__global__ __launch_bounds__(256) void scatter_kernel(
    const float* __restrict__ x,
    const int* __restrict__ rows,
    const int* __restrict__ cols)
{
    int e = blockIdx.x * 8 + (threadIdx.x >> 5);
    if (e >= N_EDGES) return;
    int lane = threadIdx.x & 31;

    int r = rows[e];
    int c = cols[e];
    float w = g_weights[c];

    float4 v = reinterpret_cast<const float4*>(x + (size_t)c * IN_DIM)[lane];
    v.x *= w; v.y *= w; v.z *= w; v.w *= w;

    float* dst = g_readout + (size_t)r * IN_DIM + lane * 4;
    asm volatile("red.global.add.v4.f32 [%0], {%1, %2, %3, %4};"
                 :: "l"(dst), "f"(v.x), "f"(v.y), "f"(v.z), "f"(v.w)
                 : "memory");
}

// ---------------------------------------------------------------------------
// MLP part 1: g_hidden = relu(readout @ W1 + b1)
// ---------------------------------------------------------------------------
__global__ __launch_bounds__(256) void mlp1_kernel(
    const float* __restrict__ W1, const float* __restrict__ b1)
{
    __shared__ float sW[IN_DIM * HIDDEN];   // 32 KB
    __shared__ float sb[HIDDEN];
    for (int i = threadIdx.x; i < IN_DIM * HIDDEN; i += 256) sW[i] = W1[i];
    if (threadIdx.x < HIDDEN) sb[threadIdx.x] = b1[threadIdx.x];
    __syncthreads();

    int node = blockIdx.x * 256 + threadIdx.x;
    if (node >= N_NODES) return;

    float t[HIDDEN];
    #pragma unroll
    for (int j = 0; j < HIDDEN; j++) t[j] = sb[j];

    const float4* r4 = reinterpret_cast<const float4*>(g_readout + (size_t)node * IN_DIM);
    for (int k4 = 0; k4 < IN_DIM / 4; k4++) {
        float4 xv = r4[k4];
        const float4* w0 = reinterpret_cast<const float4*>(sW + (k4 * 4 + 0) * HIDDEN);
        const float4* w1 = reinterpret_cast<const float4*>(sW + (k4 * 4 + 1) * HIDDEN);
        const float4* w2 = reinterpret_cast<const float4*>(sW + (k4 * 4 + 2) * HIDDEN);
        const float4* w3 = reinterpret_cast<const float4*>(sW + (k4 * 4 + 3) * HIDDEN);
        #pragma unroll
        for (int j4 = 0; j4 < HIDDEN / 4; j4++) {
            float4 a = w0[j4], b = w1[j4], c = w2[j4], d = w3[j4];
            float h0 = t[4*j4+0], h1 = t[4*j4+1], h2 = t[4*j4+2], h3 = t[4*j4+3];
            h0 = fmaf(xv.x, a.x, h0); h0 = fmaf(xv.y, b.x, h0);
            h0 = fmaf(xv.z, c.x, h0); h0 = fmaf(xv.w, d.x, h0);
            h1 = fmaf(xv.x, a.y, h1); h1 = fmaf(xv.y, b.y, h1);
            h1 = fmaf(xv.z, c.y, h1); h1 = fmaf(xv.w, d.y, h1);
            h2 = fmaf(xv.x, a.z, h2); h2 = fmaf(xv.y, b.z, h2);
            h2 = fmaf(xv.z, c.z, h2); h2 = fmaf(xv.w, d.z, h2);
            h3 = fmaf(xv.x, a.w, h3); h3 = fmaf(xv.y, b.w, h3);
            h3 = fmaf(xv.z, c.w, h3); h3 = fmaf(xv.w, d.w, h3);
            t[4*j4+0] = h0; t[4*j4+1] = h1; t[4*j4+2] = h2; t[4*j4+3] = h3;
        }
    }

    float4* o4 = reinterpret_cast<float4*>(g_hidden + (size_t)node * HIDDEN);
    #pragma unroll
    for (int j4 = 0; j4 < HIDDEN / 4; j4++) {
        float4 v;
        v.x = fmaxf(t[4*j4+0], 0.f);
        v.y = fmaxf(t[4*j4+1], 0.f);
        v.z = fmaxf(t[4*j4+2], 0.f);
        v.w = fmaxf(t[4*j4+3], 0.f);
        o4[j4] = v;
    }
}

// ---------------------------------------------------------------------------
// MLP part 2 + residual: out = x + g_hidden @ W2 + b2
// ---------------------------------------------------------------------------
__global__ __launch_bounds__(256) void mlp2_kernel(
    const float* __restrict__ x, const float* __restrict__ W2,
    const float* __restrict__ b2, float* __restrict__ out)
{
    __shared__ float sW[HIDDEN * IN_DIM];   // 32 KB
    __shared__ float sb[IN_DIM];
    for (int i = threadIdx.x; i < HIDDEN * IN_DIM; i += 256) sW[i] = W2[i];
    if (threadIdx.x < IN_DIM) sb[threadIdx.x] = b2[threadIdx.x];
    __syncthreads();

    int node = blockIdx.x * 256 + threadIdx.x;
    if (node >= N_NODES) return;

    float t[HIDDEN];
    const float4* t4 = reinterpret_cast<const float4*>(g_hidden + (size_t)node * HIDDEN);
    #pragma unroll
    for (int j4 = 0; j4 < HIDDEN / 4; j4++) {
        float4 v = t4[j4];
        t[4*j4+0] = v.x; t[4*j4+1] = v.y; t[4*j4+2] = v.z; t[4*j4+3] = v.w;
    }

    const float4* x4  = reinterpret_cast<const float4*>(x + (size_t)node * IN_DIM);
    float4*       o4  = reinterpret_cast<float4*>(out + (size_t)node * IN_DIM);
    const float4* sb4 = reinterpret_cast<const float4*>(sb);

    for (int d4 = 0; d4 < IN_DIM / 4; d4++) {
        float4 acc = x4[d4];
        float4 bb  = sb4[d4];
        acc.x += bb.x; acc.y += bb.y; acc.z += bb.z; acc.w += bb.w;
        #pragma unroll
        for (int j = 0; j < HIDDEN; j++) {
            float4 w = reinterpret_cast<const float4*>(sW + j * IN_DIM)[d4];
            float tv = t[j];
            acc.x = fmaf(tv, w.x, acc.x);
            acc.y = fmaf(tv, w.y, acc.y);
            acc.z = fmaf(tv, w.z, acc.z);
            acc.w = fmaf(tv, w.w, acc.w);
        }
        o4[d4] = acc;
    }
}

// ---------------------------------------------------------------------------
extern "C" void kernel_launch(void* const* d_in, const int* in_sizes, int n_in,
                              void* d_out, int out_size)
{
    const float* x     = (const float*)d_in[0];
    const int*   ei    = (const int*)d_in[1];   // int32: JAX x64-disabled
    const float* W_sim = (const float*)d_in[2];
    const float* b_sim = (const float*)d_in[3];
    const float* w_vec = (const float*)d_in[4];
    const float* b_vec = (const float*)d_in[5];
    const float* W1    = (const float*)d_in[6];
    const float* b1    = (const float*)d_in[7];
    const float* W2    = (const float*)d_in[8];
    const float* b2    = (const float*)d_in[9];
    float*       out   = (float*)d_out;

    const int* rows = ei;
    const int* cols = ei + N_EDGES;

    int node_blocks = (N_NODES + 255) / 256;

    zero_kernel<<<(N_NODES * IN_DIM / 4 + 255) / 256, 256>>>();
    gate_kernel<<<node_blocks, 256>>>(x, W_sim, b_sim, w_vec, b_vec);
    scatter_kernel<<<(N_EDGES + 7) / 8, 256>>>(x, rows, cols);
    mlp1_kernel<<<node_blocks, 256>>>(W1, b1);
    mlp2_kernel<<<node_blocks, 256>>>(x, W2, b2, out);
}